// round 14
// baseline (speedup 1.0000x reference)
#include <cuda_runtime.h>
#include <stdint.h>

#define NN 100000
#define EE 3200000
#define PARTITIONABLE 1
#define NB_SCAN 391          // ceil(NN/256); also k_build grid (all co-resident)
#define NT_BUILD (NB_SCAN * 256)

// ---------------- scratch (static device globals; no allocations) -------------
static __device__ float g_bufA[NN * 32];   // linear outputs (stride 32)
static __device__ float g_bufB[NN * 32];   // propagated outputs (stride 32)
static __device__ float g_dinv[NN];
static __device__ int   g_cnt[NN];
static __device__ int   g_rowptr[NN + 1];
static __device__ int   g_cursor[NN];
static __device__ int   g_col[EE];
static __device__ int   g_pos[EE];
static __device__ int   g_bsum[512];
static __device__ int   g_boff[512];
static __device__ int   g_barrier;         // grid-sync counter (reset by k_init)
static __device__ unsigned g_keys[4];
static __device__ int   g_emode;           // 0=int32, 1=int64, 2=float32

// ---------------- threefry2x32 (JAX-exact) ------------------------------------
__device__ __forceinline__ void tf2x32(unsigned k0, unsigned k1,
                                       unsigned x0, unsigned x1,
                                       unsigned &o0, unsigned &o1) {
  unsigned ks2 = k0 ^ k1 ^ 0x1BD11BDAu;
  x0 += k0; x1 += k1;
#define TF_ROUND(r) { x0 += x1; x1 = (x1 << (r)) | (x1 >> (32 - (r))); x1 ^= x0; }
  TF_ROUND(13) TF_ROUND(15) TF_ROUND(26) TF_ROUND(6)
  x0 += k1;  x1 += ks2 + 1u;
  TF_ROUND(17) TF_ROUND(29) TF_ROUND(16) TF_ROUND(24)
  x0 += ks2; x1 += k0 + 2u;
  TF_ROUND(13) TF_ROUND(15) TF_ROUND(26) TF_ROUND(6)
  x0 += k0;  x1 += k1 + 3u;
  TF_ROUND(17) TF_ROUND(29) TF_ROUND(16) TF_ROUND(24)
  x0 += k1;  x1 += ks2 + 4u;
  TF_ROUND(13) TF_ROUND(15) TF_ROUND(26) TF_ROUND(6)
  x0 += ks2; x1 += k0 + 5u;
#undef TF_ROUND
  o0 = x0; o1 = x1;
}

__device__ __forceinline__ float gumbel_at(unsigned k0, unsigned k1,
                                           unsigned idx, unsigned total) {
  unsigned bits;
#if PARTITIONABLE
  unsigned o0, o1; tf2x32(k0, k1, 0u, idx, o0, o1);
  bits = o0 ^ o1;
#else
  unsigned half = total >> 1;
  unsigned lane = (idx < half) ? idx : (idx - half);
  unsigned o0, o1; tf2x32(k0, k1, lane, lane + half, o0, o1);
  bits = (idx < half) ? o0 : o1;
#endif
  float f = __uint_as_float((bits >> 9) | 0x3F800000u) - 1.0f;
  float u = fmaxf(1.17549435e-38f, f + 1.17549435e-38f);
  return -logf(-logf(u));
}

__device__ __forceinline__ int edge_at(const void* __restrict__ ei, long long idx) {
  int m = g_emode;
  if (m == 0) return ((const int*)ei)[idx];
  if (m == 1) return (int)((const long long*)ei)[idx];
  return (int)((const float*)ei)[idx];
}

// ---------------- init: zero cnt + barrier + dtype sniff + PRNG keys ----------
__global__ void __launch_bounds__(256) k_init(const void* __restrict__ ei) {
  int i = blockIdx.x * blockDim.x + threadIdx.x;
  if (i < NN) g_cnt[i] = 0;
  if (blockIdx.x == 0 && threadIdx.x == 0) {
    g_barrier = 0;
    const unsigned* w = (const unsigned*)ei;
    int oddzero = 1;
    for (int k = 1; k < 128; k += 2) oddzero &= (w[k] == 0u);
    if (oddzero) { g_emode = 1; }
    else {
      int floaty = 1;
      for (int k = 0; k < 128; k++) {
        unsigned e = (w[k] >> 23) & 0xFFu;
        floaty &= (w[k] == 0u) || (e >= 0x70u);
      }
      g_emode = floaty ? 2 : 0;
    }
    unsigned a0, a1, b0, b1;
#if PARTITIONABLE
    tf2x32(0u, 42u, 0u, 0u, a0, a1);
    tf2x32(0u, 42u, 0u, 1u, b0, b1);
    g_keys[0] = a0; g_keys[1] = a1; g_keys[2] = b0; g_keys[3] = b1;
#else
    tf2x32(0u, 42u, 0u, 2u, a0, a1);
    tf2x32(0u, 42u, 1u, 3u, b0, b1);
    g_keys[0] = a0; g_keys[1] = b0; g_keys[2] = a1; g_keys[3] = b1;
#endif
  }
}

// ---------------- grid barrier (all NB_SCAN blocks resident) ------------------
__device__ __forceinline__ void gsync(int phase) {
  __syncthreads();
  __threadfence();
  if (threadIdx.x == 0) {
    atomicAdd(&g_barrier, 1);
    while (*(volatile int*)&g_barrier < NB_SCAN * phase) {}
  }
  __syncthreads();
}

// ---------------- fused hist + scan + fill (one persistent kernel) ------------
__global__ void __launch_bounds__(256) k_build(const void* __restrict__ ei) {
  int t = threadIdx.x;
  int tid = blockIdx.x * 256 + t;

  // phase 0: histogram (grid-strided, coalesced)
  for (long long e = tid; e < EE; e += NT_BUILD) {
    int d = edge_at(ei, (long long)EE + e);
    if ((unsigned)d < NN) atomicAdd(&g_cnt[d], 1);
  }
  gsync(1);

  // phase 1: per-block inclusive scan of this block's 256 counts
  __shared__ int sp[512];
  int i = blockIdx.x * 256 + t;
  int c = (i < NN) ? g_cnt[i] : 0;
  sp[t] = c;
  __syncthreads();
  for (int off = 1; off < 256; off <<= 1) {
    int a = sp[t];
    int b = (t >= off) ? sp[t - off] : 0;
    __syncthreads();
    sp[t] = a + b;
    __syncthreads();
  }
  int blocktot = sp[255];
  int myincl = sp[t];
  if (t == 0) g_bsum[blockIdx.x] = blocktot;
  gsync(2);

  // phase 2: block 0 scans the 391 block sums (512-wide scan, 2 elems/thread)
  if (blockIdx.x == 0) {
    __syncthreads();
    int v0 = (t < NB_SCAN) ? g_bsum[t] : 0;
    int v1 = (t + 256 < NB_SCAN) ? g_bsum[t + 256] : 0;
    sp[t] = v0; sp[t + 256] = v1;
    __syncthreads();
    for (int off = 1; off < 512; off <<= 1) {
      int a0 = sp[t], a1 = sp[t + 256];
      int b0 = (t >= off) ? sp[t - off] : 0;
      int b1 = (t + 256 >= off) ? sp[t + 256 - off] : 0;
      __syncthreads();
      sp[t] = a0 + b0; sp[t + 256] = a1 + b1;
      __syncthreads();
    }
    if (t < NB_SCAN) g_boff[t] = sp[t] - v0;
    if (t + 256 < NB_SCAN) g_boff[t + 256] = sp[t + 256] - v1;
    if (t == 0) g_rowptr[NN] = sp[NB_SCAN - 1];
  }
  gsync(3);

  // phase 3: rowptr + cursor + dinv
  if (i < NN) {
    int excl = myincl - c + g_boff[blockIdx.x];
    g_rowptr[i] = excl;
    g_cursor[i] = excl;
    g_dinv[i] = 1.0f / sqrtf((float)c + 1.0f);   // matches reference bit-for-bit
  }
  gsync(4);

  // phase 4: fill (grid-strided)
  for (long long e = tid; e < EE; e += NT_BUILD) {
    int s = edge_at(ei, e);
    int d = edge_at(ei, (long long)EE + e);
    if ((unsigned)d < NN && (unsigned)s < NN) {
      int p = atomicAdd(&g_cursor[d], 1);
      g_col[p] = s;
      g_pos[p] = (int)e;
    }
  }
}

// restore per-node ORIGINAL EDGE ORDER (sort by pos) -> matches XLA scatter order
__global__ void __launch_bounds__(256) k_sort() {
  __shared__ int sp_[8][128];
  __shared__ int sc_[8][128];
  int wid = threadIdx.x >> 5, lane = threadIdx.x & 31;
  int v = blockIdx.x * 8 + wid;
  if (v >= NN) return;
  int s = g_rowptr[v], e = g_rowptr[v + 1], d = e - s;
  if (d <= 1) return;
  if (d <= 128) {
    int* ap = sp_[wid];
    int* ac = sc_[wid];
    for (int i = lane; i < d; i += 32) { ap[i] = g_pos[s + i]; ac[i] = g_col[s + i]; }
    __syncwarp();
    for (int p = 0; p < d; p++) {
      for (int i = (p & 1) + 2 * lane; i + 1 < d; i += 64) {
        int pa = ap[i], pb = ap[i + 1];
        if (pa > pb) {
          ap[i] = pb; ap[i + 1] = pa;
          int ca = ac[i]; ac[i] = ac[i + 1]; ac[i + 1] = ca;
        }
      }
      __syncwarp();
    }
    for (int i = lane; i < d; i += 32) g_col[s + i] = ac[i];
  } else {
    if (lane == 0) {
      for (int i = s + 1; i < e; i++) {
        int kp = g_pos[i], kc = g_col[i]; int j = i - 1;
        while (j >= s && g_pos[j] > kp) {
          g_pos[j + 1] = g_pos[j]; g_col[j + 1] = g_col[j]; j--;
        }
        g_pos[j + 1] = kp; g_col[j + 1] = kc;
      }
    }
  }
}

// ---------------- GCN linear: out(bufA) = in @ W  (no bias here) --------------
template<int K, int F, int INSTRIDE, int SRC>
__global__ void __launch_bounds__(128) k_lin(const float* __restrict__ xin,
                                             const float* __restrict__ W) {
  __shared__ float sW[K * F];
  for (int i = threadIdx.x; i < K * F; i += blockDim.x) sW[i] = W[i];
  __syncthreads();
  int v = blockIdx.x * blockDim.x + threadIdx.x;
  if (v >= NN) return;
  const float* in = (SRC == 0) ? (xin + (size_t)v * INSTRIDE)
                               : (g_bufB + (size_t)v * INSTRIDE);
  float acc[F];
#pragma unroll
  for (int f = 0; f < F; f++) acc[f] = 0.f;
#pragma unroll 4
  for (int k = 0; k < K; k++) {
    float xv = in[k];
#pragma unroll
    for (int f = 0; f < F; f++) acc[f] = fmaf(xv, sW[k * F + f], acc[f]);
  }
  float* o = g_bufA + (size_t)v * 32;
#pragma unroll
  for (int f = 0; f < F; f++) o[f] = acc[f];
}

// ---------------- propagate F=16: 2 nodes per warp, unroll-4 exact order ------
__global__ void __launch_bounds__(256) k_prop16(const float* __restrict__ b) {
  int gw = (blockIdx.x * blockDim.x + threadIdx.x) >> 5;
  int lane = threadIdx.x & 31;
  int half = lane >> 4;
  int l = lane & 15;
  int v = gw * 2 + half;
  if (v >= NN) return;
  float dv = g_dinv[v];
  int s = g_rowptr[v], e = g_rowptr[v + 1];
  float acc = 0.f;
  int j = s;
  for (; j + 3 < e; j += 4) {
    int u0 = g_col[j], u1 = g_col[j + 1], u2 = g_col[j + 2], u3 = g_col[j + 3];
    float w0 = __fmul_rn(g_dinv[u0], dv);
    float w1 = __fmul_rn(g_dinv[u1], dv);
    float w2 = __fmul_rn(g_dinv[u2], dv);
    float w3 = __fmul_rn(g_dinv[u3], dv);
    float h0 = g_bufA[u0 * 32 + l];
    float h1 = g_bufA[u1 * 32 + l];
    float h2 = g_bufA[u2 * 32 + l];
    float h3 = g_bufA[u3 * 32 + l];
    acc = __fadd_rn(acc, __fmul_rn(h0, w0));    // exact sequential order kept
    acc = __fadd_rn(acc, __fmul_rn(h1, w1));
    acc = __fadd_rn(acc, __fmul_rn(h2, w2));
    acc = __fadd_rn(acc, __fmul_rn(h3, w3));
  }
  for (; j < e; j++) {
    int u = g_col[j];
    float w = __fmul_rn(g_dinv[u], dv);
    acc = __fadd_rn(acc, __fmul_rn(g_bufA[u * 32 + l], w));
  }
  float sl = __fmul_rn(dv, dv);
  acc = __fadd_rn(acc, __fmul_rn(g_bufA[v * 32 + l], sl));
  g_bufB[v * 32 + l] = __fadd_rn(acc, b[l]);
}

// ---------------- propagate general (warp per node), unroll-4 exact order -----
template<int F>
__global__ void __launch_bounds__(256) k_prop(const float* __restrict__ b) {
  int gw = (blockIdx.x * blockDim.x + threadIdx.x) >> 5;
  int lane = threadIdx.x & 31;
  if (gw >= NN) return;
  int v = gw;
  float dv = g_dinv[v];
  int s = g_rowptr[v], e = g_rowptr[v + 1];
  float acc = 0.f;
  int j = s;
  for (; j + 3 < e; j += 4) {
    int u0 = g_col[j], u1 = g_col[j + 1], u2 = g_col[j + 2], u3 = g_col[j + 3];
    float w0 = __fmul_rn(g_dinv[u0], dv);
    float w1 = __fmul_rn(g_dinv[u1], dv);
    float w2 = __fmul_rn(g_dinv[u2], dv);
    float w3 = __fmul_rn(g_dinv[u3], dv);
    float h0 = (lane < F) ? g_bufA[u0 * 32 + lane] : 0.f;
    float h1 = (lane < F) ? g_bufA[u1 * 32 + lane] : 0.f;
    float h2 = (lane < F) ? g_bufA[u2 * 32 + lane] : 0.f;
    float h3 = (lane < F) ? g_bufA[u3 * 32 + lane] : 0.f;
    acc = __fadd_rn(acc, __fmul_rn(h0, w0));
    acc = __fadd_rn(acc, __fmul_rn(h1, w1));
    acc = __fadd_rn(acc, __fmul_rn(h2, w2));
    acc = __fadd_rn(acc, __fmul_rn(h3, w3));
  }
  for (; j < e; j++) {
    int u = g_col[j];
    float w = __fmul_rn(g_dinv[u], dv);
    float hv = (lane < F) ? g_bufA[u * 32 + lane] : 0.f;
    acc = __fadd_rn(acc, __fmul_rn(hv, w));
  }
  if (lane < F) {
    float sl = __fmul_rn(dv, dv);
    acc = __fadd_rn(acc, __fmul_rn(g_bufA[v * 32 + lane], sl));
    g_bufB[v * 32 + lane] = __fadd_rn(acc, b[lane]);
  }
}

// ---------------- start head --------------------------------------------------
__global__ void __launch_bounds__(128) k_start(
    const float* __restrict__ Ws1, const float* __restrict__ bs1,
    const float* __restrict__ Ws2, const float* __restrict__ bs2,
    float* __restrict__ outp) {
  __shared__ float sW1[512], sW2[512], sb1[16], sb2[32];
  for (int i = threadIdx.x; i < 512; i += blockDim.x) { sW1[i] = Ws1[i]; sW2[i] = Ws2[i]; }
  if (threadIdx.x < 16) sb1[threadIdx.x] = bs1[threadIdx.x];
  if (threadIdx.x < 32) sb2[threadIdx.x] = bs2[threadIdx.x];
  __syncthreads();
  int v = blockIdx.x * blockDim.x + threadIdx.x;
  if (v >= NN) return;
  float hr[32];
#pragma unroll
  for (int k = 0; k < 32; k++) hr[k] = g_bufB[v * 32 + k];
  float t[16];
#pragma unroll
  for (int j = 0; j < 16; j++) {
    float a = 0.f;
#pragma unroll
    for (int k = 0; k < 32; k++) a = fmaf(hr[k], sW1[k * 16 + j], a);
    a += sb1[j];
    t[j] = fminf(fmaxf(a, 0.f), 6.f);
  }
  unsigned k0 = g_keys[0], k1 = g_keys[1];
  float best = -1e30f; int bi = 0;
  for (int c = 0; c < 32; c++) {
    float l = 0.f;
#pragma unroll
    for (int j = 0; j < 16; j++) l = fmaf(t[j], sW2[j * 32 + c], l);
    l += sb2[c];
    float val = l + gumbel_at(k0, k1, (unsigned)(v * 32 + c), (unsigned)NN * 32u);
    if (val > best) { best = val; bi = c; }
  }
  outp[v] = (float)bi;
}

// ---------------- end head ----------------------------------------------------
__global__ void __launch_bounds__(128) k_end(
    const float* __restrict__ We1, const float* __restrict__ be1,
    const float* __restrict__ We2, const float* __restrict__ be2,
    float* __restrict__ outp) {
  __shared__ float sW1[768], sW2[768], sb1[24], sb2[32];
  for (int i = threadIdx.x; i < 768; i += blockDim.x) { sW1[i] = We1[i]; sW2[i] = We2[i]; }
  if (threadIdx.x < 24) sb1[threadIdx.x] = be1[threadIdx.x];
  if (threadIdx.x < 32) sb2[threadIdx.x] = be2[threadIdx.x];
  __syncthreads();
  int v = blockIdx.x * blockDim.x + threadIdx.x;
  if (v >= 2 * NN) return;
  int row = (v < NN) ? v : (int)outp[v - NN];
  float hr[32];
#pragma unroll
  for (int k = 0; k < 32; k++) hr[k] = g_bufB[row * 32 + k];
  float t[24];
#pragma unroll
  for (int j = 0; j < 24; j++) {
    float a = 0.f;
#pragma unroll
    for (int k = 0; k < 32; k++) a = fmaf(hr[k], sW1[k * 24 + j], a);
    a += sb1[j];
    t[j] = fminf(fmaxf(a, 0.f), 6.f);
  }
  unsigned k0 = g_keys[2], k1 = g_keys[3];
  float best = -1e30f; int bi = 0;
  for (int c = 0; c < 32; c++) {
    float l = 0.f;
#pragma unroll
    for (int j = 0; j < 24; j++) l = fmaf(t[j], sW2[j * 32 + c], l);
    l += sb2[c];
    float val = l + gumbel_at(k0, k1, (unsigned)(v * 32 + c), 2u * (unsigned)NN * 32u);
    if (val > best) { best = val; bi = c; }
  }
  outp[(long long)NN + v] = (float)bi;
}

// ---------------- launch ------------------------------------------------------
extern "C" void kernel_launch(void* const* d_in, const int* in_sizes, int n_in,
                              void* d_out, int out_size) {
  (void)out_size;
  static const int SZ_DICT[17] = {12800000, 6400000, 32, 2048, 16, 384, 24,
                                  768, 32, 512, 16, 512, 32, 768, 24, 768, 32};
  static const int SZ_ALPHA[17] = {2048, 384, 768, 768, 768, 512, 512, 16, 24,
                                   32, 24, 32, 16, 32, 32, 6400000, 12800000};
  int match_dict = (n_in >= 17), match_alpha = (n_in >= 17);
  for (int i = 0; i < 17 && i < n_in; i++) {
    if (in_sizes[i] != SZ_DICT[i])  match_dict = 0;
    if (in_sizes[i] != SZ_ALPHA[i]) match_alpha = 0;
  }

  const float *x, *W1, *b1, *W2, *b2, *W3, *b3;
  const float *Ws1, *bs1, *Ws2, *bs2, *We1, *be1, *We2, *be2;
  const void* ei;
  if (match_alpha && !match_dict) {
    W1  = (const float*)d_in[0];  W2  = (const float*)d_in[1];
    W3  = (const float*)d_in[2];  We1 = (const float*)d_in[3];
    We2 = (const float*)d_in[4];  Ws1 = (const float*)d_in[5];
    Ws2 = (const float*)d_in[6];  b1  = (const float*)d_in[7];
    b2  = (const float*)d_in[8];  b3  = (const float*)d_in[9];
    be1 = (const float*)d_in[10]; be2 = (const float*)d_in[11];
    bs1 = (const float*)d_in[12]; bs2 = (const float*)d_in[13];
    ei  = d_in[15];               x   = (const float*)d_in[16];
  } else {
    x   = (const float*)d_in[0];  ei  = d_in[1];
    W1  = (const float*)d_in[3];  b1  = (const float*)d_in[4];
    W2  = (const float*)d_in[5];  b2  = (const float*)d_in[6];
    W3  = (const float*)d_in[7];  b3  = (const float*)d_in[8];
    Ws1 = (const float*)d_in[9];  bs1 = (const float*)d_in[10];
    Ws2 = (const float*)d_in[11]; bs2 = (const float*)d_in[12];
    We1 = (const float*)d_in[13]; be1 = (const float*)d_in[14];
    We2 = (const float*)d_in[15]; be2 = (const float*)d_in[16];
  }
  float* out = (float*)d_out;

  const int TB = 256;
  const int GB_W = (NN * 32 + TB - 1) / TB;      // warp-per-node: 12500
  const int GB_W2 = (NN * 16 + TB - 1) / TB;     // 2 nodes/warp: 6250

  k_init<<<NB_SCAN, 256>>>(ei);                              // 0
  k_lin<128, 16, 128, 0><<<(NN + 127) / 128, 128>>>(x, W1);  // 1 (independent)
  k_build<<<NB_SCAN, 256>>>(ei);                             // 2
  k_sort<<<(NN + 7) / 8, 256>>>();                           // 3 <-- ncu capture

  k_prop16<<<GB_W2, TB>>>(b1);
  k_lin<16, 24, 32, 1><<<(NN + 127) / 128, 128>>>(nullptr, W2);
  k_prop<24><<<GB_W, TB>>>(b2);
  k_lin<24, 32, 32, 1><<<(NN + 127) / 128, 128>>>(nullptr, W3);
  k_prop<32><<<GB_W, TB>>>(b3);

  k_start<<<(NN + 127) / 128, 128>>>(Ws1, bs1, Ws2, bs2, out);
  k_end<<<(2 * NN + 127) / 128, 128>>>(We1, be1, We2, be2, out);
}

// round 15
// speedup vs baseline: 1.0699x; 1.0699x over previous
#include <cuda_runtime.h>
#include <stdint.h>

#define NN 100000
#define EE 3200000
#define PARTITIONABLE 1
#define NB_SCAN 391          // ceil(NN/256); also k_build grid (all co-resident)
#define NT_BUILD (NB_SCAN * 256)
#define COLBITS 17

// ---------------- scratch (static device globals; no allocations) -------------
static __device__ float g_bufA[NN * 32];   // linear outputs (stride 32)
static __device__ float g_bufB[NN * 32];   // propagated outputs (stride 32)
static __device__ float g_dinv[NN];
static __device__ int   g_cnt[NN];
static __device__ int   g_rowptr[NN + 1];
static __device__ int   g_cursor[NN];
static __device__ int   g_col[EE];
static __device__ int   g_pos[EE];
static __device__ int   g_bsum[512];
static __device__ int   g_boff[512];
static __device__ int   g_barrier;         // grid-sync counter (reset by k_init)
static __device__ unsigned g_keys[4];
static __device__ int   g_emode;           // 0=int32, 1=int64, 2=float32

// ---------------- threefry2x32 (JAX-exact) ------------------------------------
__device__ __forceinline__ void tf2x32(unsigned k0, unsigned k1,
                                       unsigned x0, unsigned x1,
                                       unsigned &o0, unsigned &o1) {
  unsigned ks2 = k0 ^ k1 ^ 0x1BD11BDAu;
  x0 += k0; x1 += k1;
#define TF_ROUND(r) { x0 += x1; x1 = (x1 << (r)) | (x1 >> (32 - (r))); x1 ^= x0; }
  TF_ROUND(13) TF_ROUND(15) TF_ROUND(26) TF_ROUND(6)
  x0 += k1;  x1 += ks2 + 1u;
  TF_ROUND(17) TF_ROUND(29) TF_ROUND(16) TF_ROUND(24)
  x0 += ks2; x1 += k0 + 2u;
  TF_ROUND(13) TF_ROUND(15) TF_ROUND(26) TF_ROUND(6)
  x0 += k0;  x1 += k1 + 3u;
  TF_ROUND(17) TF_ROUND(29) TF_ROUND(16) TF_ROUND(24)
  x0 += k1;  x1 += ks2 + 4u;
  TF_ROUND(13) TF_ROUND(15) TF_ROUND(26) TF_ROUND(6)
  x0 += ks2; x1 += k0 + 5u;
#undef TF_ROUND
  o0 = x0; o1 = x1;
}

__device__ __forceinline__ float gumbel_at(unsigned k0, unsigned k1,
                                           unsigned idx, unsigned total) {
  unsigned bits;
#if PARTITIONABLE
  unsigned o0, o1; tf2x32(k0, k1, 0u, idx, o0, o1);
  bits = o0 ^ o1;
#else
  unsigned half = total >> 1;
  unsigned lane = (idx < half) ? idx : (idx - half);
  unsigned o0, o1; tf2x32(k0, k1, lane, lane + half, o0, o1);
  bits = (idx < half) ? o0 : o1;
#endif
  float f = __uint_as_float((bits >> 9) | 0x3F800000u) - 1.0f;
  float u = fmaxf(1.17549435e-38f, f + 1.17549435e-38f);
  return -logf(-logf(u));
}

__device__ __forceinline__ int edge_at(const void* __restrict__ ei, long long idx) {
  int m = g_emode;
  if (m == 0) return ((const int*)ei)[idx];
  if (m == 1) return (int)((const long long*)ei)[idx];
  return (int)((const float*)ei)[idx];
}

// ---------------- init: zero cnt + barrier + dtype sniff + PRNG keys ----------
__global__ void __launch_bounds__(256) k_init(const void* __restrict__ ei) {
  int i = blockIdx.x * blockDim.x + threadIdx.x;
  if (i < NN) g_cnt[i] = 0;
  if (blockIdx.x == 0 && threadIdx.x == 0) {
    g_barrier = 0;
    const unsigned* w = (const unsigned*)ei;
    int oddzero = 1;
    for (int k = 1; k < 128; k += 2) oddzero &= (w[k] == 0u);
    if (oddzero) { g_emode = 1; }
    else {
      int floaty = 1;
      for (int k = 0; k < 128; k++) {
        unsigned e = (w[k] >> 23) & 0xFFu;
        floaty &= (w[k] == 0u) || (e >= 0x70u);
      }
      g_emode = floaty ? 2 : 0;
    }
    unsigned a0, a1, b0, b1;
#if PARTITIONABLE
    tf2x32(0u, 42u, 0u, 0u, a0, a1);
    tf2x32(0u, 42u, 0u, 1u, b0, b1);
    g_keys[0] = a0; g_keys[1] = a1; g_keys[2] = b0; g_keys[3] = b1;
#else
    tf2x32(0u, 42u, 0u, 2u, a0, a1);
    tf2x32(0u, 42u, 1u, 3u, b0, b1);
    g_keys[0] = a0; g_keys[1] = b0; g_keys[2] = a1; g_keys[3] = b1;
#endif
  }
}

// ---------------- grid barrier (all NB_SCAN blocks resident) ------------------
__device__ __forceinline__ void gsync(int phase) {
  __syncthreads();
  __threadfence();
  if (threadIdx.x == 0) {
    atomicAdd(&g_barrier, 1);
    while (*(volatile int*)&g_barrier < NB_SCAN * phase) {}
  }
  __syncthreads();
}

// ---------------- fused hist + scan + fill (one persistent kernel) ------------
__global__ void __launch_bounds__(256) k_build(const void* __restrict__ ei) {
  int t = threadIdx.x;
  int tid = blockIdx.x * 256 + t;

  // phase 0: histogram (grid-strided, coalesced)
  for (long long e = tid; e < EE; e += NT_BUILD) {
    int d = edge_at(ei, (long long)EE + e);
    if ((unsigned)d < NN) atomicAdd(&g_cnt[d], 1);
  }
  gsync(1);

  // phase 1: per-block inclusive scan of this block's 256 counts
  __shared__ int sp[512];
  int i = blockIdx.x * 256 + t;
  int c = (i < NN) ? g_cnt[i] : 0;
  sp[t] = c;
  __syncthreads();
  for (int off = 1; off < 256; off <<= 1) {
    int a = sp[t];
    int b = (t >= off) ? sp[t - off] : 0;
    __syncthreads();
    sp[t] = a + b;
    __syncthreads();
  }
  int blocktot = sp[255];
  int myincl = sp[t];
  if (t == 0) g_bsum[blockIdx.x] = blocktot;
  gsync(2);

  // phase 2: block 0 scans the 391 block sums
  if (blockIdx.x == 0) {
    __syncthreads();
    int v0 = (t < NB_SCAN) ? g_bsum[t] : 0;
    int v1 = (t + 256 < NB_SCAN) ? g_bsum[t + 256] : 0;
    sp[t] = v0; sp[t + 256] = v1;
    __syncthreads();
    for (int off = 1; off < 512; off <<= 1) {
      int a0 = sp[t], a1 = sp[t + 256];
      int b0 = (t >= off) ? sp[t - off] : 0;
      int b1 = (t + 256 >= off) ? sp[t + 256 - off] : 0;
      __syncthreads();
      sp[t] = a0 + b0; sp[t + 256] = a1 + b1;
      __syncthreads();
    }
    if (t < NB_SCAN) g_boff[t] = sp[t] - v0;
    if (t + 256 < NB_SCAN) g_boff[t + 256] = sp[t + 256] - v1;
    if (t == 0) g_rowptr[NN] = sp[NB_SCAN - 1];
  }
  gsync(3);

  // phase 3: rowptr + cursor + dinv
  if (i < NN) {
    int excl = myincl - c + g_boff[blockIdx.x];
    g_rowptr[i] = excl;
    g_cursor[i] = excl;
    g_dinv[i] = 1.0f / sqrtf((float)c + 1.0f);   // matches reference bit-for-bit
  }
  gsync(4);

  // phase 4: fill (grid-strided)
  for (long long e = tid; e < EE; e += NT_BUILD) {
    int s = edge_at(ei, e);
    int d = edge_at(ei, (long long)EE + e);
    if ((unsigned)d < NN && (unsigned)s < NN) {
      int p = atomicAdd(&g_cursor[d], 1);
      g_col[p] = s;
      g_pos[p] = (int)e;
    }
  }
}

// ---------------- sort: warp-register bitonic (64-wide) on packed (pos,col) ---
__global__ void __launch_bounds__(256) k_sort() {
  __shared__ int sp_[8][128];
  __shared__ int sc_[8][128];
  int wid = threadIdx.x >> 5, lane = threadIdx.x & 31;
  int v = blockIdx.x * 8 + wid;
  if (v >= NN) return;
  int s = g_rowptr[v], e = g_rowptr[v + 1], d = e - s;
  if (d <= 1) return;
  if (d <= 64) {
    const unsigned long long PADV = ~0ULL;
    unsigned long long a0 = PADV, a1 = PADV;
    if (lane < d)
      a0 = ((unsigned long long)(unsigned)g_pos[s + lane] << COLBITS) |
           (unsigned)g_col[s + lane];
    if (lane + 32 < d)
      a1 = ((unsigned long long)(unsigned)g_pos[s + lane + 32] << COLBITS) |
           (unsigned)g_col[s + lane + 32];
    // bitonic sort, 64 elements: i0 = lane, i1 = 32 + lane
#pragma unroll
    for (int k = 2; k <= 64; k <<= 1) {
#pragma unroll
      for (int j = 32; j > 0; j >>= 1) {
        if (j >= k) continue;
        if (j == 32) {
          // k == 64 only: in-lane exchange, dir ascending, i0 < i1
          unsigned long long mn = a0 < a1 ? a0 : a1;
          unsigned long long mx = a0 < a1 ? a1 : a0;
          a0 = mn; a1 = mx;
        } else {
          unsigned long long o0 = __shfl_xor_sync(0xFFFFFFFFu, a0, j);
          unsigned long long o1 = __shfl_xor_sync(0xFFFFFFFFu, a1, j);
          bool lower = ((lane & j) == 0);
          bool up0, up1;
          if (k == 64)      { up0 = true;               up1 = true; }
          else if (k == 32) { up0 = true;               up1 = false; }
          else              { up0 = ((lane & k) == 0);  up1 = up0; }
          unsigned long long mn0 = a0 < o0 ? a0 : o0;
          unsigned long long mx0 = a0 < o0 ? o0 : a0;
          unsigned long long mn1 = a1 < o1 ? a1 : o1;
          unsigned long long mx1 = a1 < o1 ? o1 : a1;
          a0 = (lower == up0) ? mn0 : mx0;
          a1 = (lower == up1) ? mn1 : mx1;
        }
      }
    }
    if (lane < d)      g_col[s + lane]      = (int)(a0 & ((1u << COLBITS) - 1));
    if (lane + 32 < d) g_col[s + lane + 32] = (int)(a1 & ((1u << COLBITS) - 1));
  } else if (d <= 128) {
    int* ap = sp_[wid];
    int* ac = sc_[wid];
    for (int i = lane; i < d; i += 32) { ap[i] = g_pos[s + i]; ac[i] = g_col[s + i]; }
    __syncwarp();
    for (int p = 0; p < d; p++) {
      for (int i = (p & 1) + 2 * lane; i + 1 < d; i += 64) {
        int pa = ap[i], pb = ap[i + 1];
        if (pa > pb) {
          ap[i] = pb; ap[i + 1] = pa;
          int ca = ac[i]; ac[i] = ac[i + 1]; ac[i + 1] = ca;
        }
      }
      __syncwarp();
    }
    for (int i = lane; i < d; i += 32) g_col[s + i] = ac[i];
  } else {
    if (lane == 0) {
      for (int i = s + 1; i < e; i++) {
        int kp = g_pos[i], kc = g_col[i]; int j = i - 1;
        while (j >= s && g_pos[j] > kp) {
          g_pos[j + 1] = g_pos[j]; g_col[j + 1] = g_col[j]; j--;
        }
        g_pos[j + 1] = kp; g_col[j + 1] = kc;
      }
    }
  }
}

// ---------------- GCN linear: out(bufA) = in @ W  (no bias here) --------------
template<int K, int F, int INSTRIDE, int SRC>
__global__ void __launch_bounds__(128) k_lin(const float* __restrict__ xin,
                                             const float* __restrict__ W) {
  __shared__ float sW[K * F];
  for (int i = threadIdx.x; i < K * F; i += blockDim.x) sW[i] = W[i];
  __syncthreads();
  int v = blockIdx.x * blockDim.x + threadIdx.x;
  if (v >= NN) return;
  const float* in = (SRC == 0) ? (xin + (size_t)v * INSTRIDE)
                               : (g_bufB + (size_t)v * INSTRIDE);
  float acc[F];
#pragma unroll
  for (int f = 0; f < F; f++) acc[f] = 0.f;
#pragma unroll 4
  for (int k = 0; k < K; k++) {
    float xv = in[k];
#pragma unroll
    for (int f = 0; f < F; f++) acc[f] = fmaf(xv, sW[k * F + f], acc[f]);
  }
  float* o = g_bufA + (size_t)v * 32;
#pragma unroll
  for (int f = 0; f < F; f++) o[f] = acc[f];
}

// ---------------- propagate F=16: 2 nodes per warp, unroll-4 exact order ------
__global__ void __launch_bounds__(256) k_prop16(const float* __restrict__ b) {
  int gw = (blockIdx.x * blockDim.x + threadIdx.x) >> 5;
  int lane = threadIdx.x & 31;
  int half = lane >> 4;
  int l = lane & 15;
  int v = gw * 2 + half;
  if (v >= NN) return;
  float dv = g_dinv[v];
  int s = g_rowptr[v], e = g_rowptr[v + 1];
  float acc = 0.f;
  int j = s;
  for (; j + 3 < e; j += 4) {
    int u0 = g_col[j], u1 = g_col[j + 1], u2 = g_col[j + 2], u3 = g_col[j + 3];
    float w0 = __fmul_rn(g_dinv[u0], dv);
    float w1 = __fmul_rn(g_dinv[u1], dv);
    float w2 = __fmul_rn(g_dinv[u2], dv);
    float w3 = __fmul_rn(g_dinv[u3], dv);
    float h0 = g_bufA[u0 * 32 + l];
    float h1 = g_bufA[u1 * 32 + l];
    float h2 = g_bufA[u2 * 32 + l];
    float h3 = g_bufA[u3 * 32 + l];
    acc = __fadd_rn(acc, __fmul_rn(h0, w0));    // exact sequential order kept
    acc = __fadd_rn(acc, __fmul_rn(h1, w1));
    acc = __fadd_rn(acc, __fmul_rn(h2, w2));
    acc = __fadd_rn(acc, __fmul_rn(h3, w3));
  }
  for (; j < e; j++) {
    int u = g_col[j];
    float w = __fmul_rn(g_dinv[u], dv);
    acc = __fadd_rn(acc, __fmul_rn(g_bufA[u * 32 + l], w));
  }
  float sl = __fmul_rn(dv, dv);
  acc = __fadd_rn(acc, __fmul_rn(g_bufA[v * 32 + l], sl));
  g_bufB[v * 32 + l] = __fadd_rn(acc, b[l]);
}

// ---------------- propagate general (warp per node), unroll-4 exact order -----
template<int F>
__global__ void __launch_bounds__(256) k_prop(const float* __restrict__ b) {
  int gw = (blockIdx.x * blockDim.x + threadIdx.x) >> 5;
  int lane = threadIdx.x & 31;
  if (gw >= NN) return;
  int v = gw;
  float dv = g_dinv[v];
  int s = g_rowptr[v], e = g_rowptr[v + 1];
  float acc = 0.f;
  int j = s;
  for (; j + 3 < e; j += 4) {
    int u0 = g_col[j], u1 = g_col[j + 1], u2 = g_col[j + 2], u3 = g_col[j + 3];
    float w0 = __fmul_rn(g_dinv[u0], dv);
    float w1 = __fmul_rn(g_dinv[u1], dv);
    float w2 = __fmul_rn(g_dinv[u2], dv);
    float w3 = __fmul_rn(g_dinv[u3], dv);
    float h0 = (lane < F) ? g_bufA[u0 * 32 + lane] : 0.f;
    float h1 = (lane < F) ? g_bufA[u1 * 32 + lane] : 0.f;
    float h2 = (lane < F) ? g_bufA[u2 * 32 + lane] : 0.f;
    float h3 = (lane < F) ? g_bufA[u3 * 32 + lane] : 0.f;
    acc = __fadd_rn(acc, __fmul_rn(h0, w0));
    acc = __fadd_rn(acc, __fmul_rn(h1, w1));
    acc = __fadd_rn(acc, __fmul_rn(h2, w2));
    acc = __fadd_rn(acc, __fmul_rn(h3, w3));
  }
  for (; j < e; j++) {
    int u = g_col[j];
    float w = __fmul_rn(g_dinv[u], dv);
    float hv = (lane < F) ? g_bufA[u * 32 + lane] : 0.f;
    acc = __fadd_rn(acc, __fmul_rn(hv, w));
  }
  if (lane < F) {
    float sl = __fmul_rn(dv, dv);
    acc = __fadd_rn(acc, __fmul_rn(g_bufA[v * 32 + lane], sl));
    g_bufB[v * 32 + lane] = __fadd_rn(acc, b[lane]);
  }
}

// ---------------- start head --------------------------------------------------
__global__ void __launch_bounds__(128) k_start(
    const float* __restrict__ Ws1, const float* __restrict__ bs1,
    const float* __restrict__ Ws2, const float* __restrict__ bs2,
    float* __restrict__ outp) {
  __shared__ float sW1[512], sW2[512], sb1[16], sb2[32];
  for (int i = threadIdx.x; i < 512; i += blockDim.x) { sW1[i] = Ws1[i]; sW2[i] = Ws2[i]; }
  if (threadIdx.x < 16) sb1[threadIdx.x] = bs1[threadIdx.x];
  if (threadIdx.x < 32) sb2[threadIdx.x] = bs2[threadIdx.x];
  __syncthreads();
  int v = blockIdx.x * blockDim.x + threadIdx.x;
  if (v >= NN) return;
  float hr[32];
#pragma unroll
  for (int k = 0; k < 32; k++) hr[k] = g_bufB[v * 32 + k];
  float t[16];
#pragma unroll
  for (int j = 0; j < 16; j++) {
    float a = 0.f;
#pragma unroll
    for (int k = 0; k < 32; k++) a = fmaf(hr[k], sW1[k * 16 + j], a);
    a += sb1[j];
    t[j] = fminf(fmaxf(a, 0.f), 6.f);
  }
  unsigned k0 = g_keys[0], k1 = g_keys[1];
  float best = -1e30f; int bi = 0;
  for (int c = 0; c < 32; c++) {
    float l = 0.f;
#pragma unroll
    for (int j = 0; j < 16; j++) l = fmaf(t[j], sW2[j * 32 + c], l);
    l += sb2[c];
    float val = l + gumbel_at(k0, k1, (unsigned)(v * 32 + c), (unsigned)NN * 32u);
    if (val > best) { best = val; bi = c; }
  }
  outp[v] = (float)bi;
}

// ---------------- end head ----------------------------------------------------
__global__ void __launch_bounds__(128) k_end(
    const float* __restrict__ We1, const float* __restrict__ be1,
    const float* __restrict__ We2, const float* __restrict__ be2,
    float* __restrict__ outp) {
  __shared__ float sW1[768], sW2[768], sb1[24], sb2[32];
  for (int i = threadIdx.x; i < 768; i += blockDim.x) { sW1[i] = We1[i]; sW2[i] = We2[i]; }
  if (threadIdx.x < 24) sb1[threadIdx.x] = be1[threadIdx.x];
  if (threadIdx.x < 32) sb2[threadIdx.x] = be2[threadIdx.x];
  __syncthreads();
  int v = blockIdx.x * blockDim.x + threadIdx.x;
  if (v >= 2 * NN) return;
  int row = (v < NN) ? v : (int)outp[v - NN];
  float hr[32];
#pragma unroll
  for (int k = 0; k < 32; k++) hr[k] = g_bufB[row * 32 + k];
  float t[24];
#pragma unroll
  for (int j = 0; j < 24; j++) {
    float a = 0.f;
#pragma unroll
    for (int k = 0; k < 32; k++) a = fmaf(hr[k], sW1[k * 24 + j], a);
    a += sb1[j];
    t[j] = fminf(fmaxf(a, 0.f), 6.f);
  }
  unsigned k0 = g_keys[2], k1 = g_keys[3];
  float best = -1e30f; int bi = 0;
  for (int c = 0; c < 32; c++) {
    float l = 0.f;
#pragma unroll
    for (int j = 0; j < 24; j++) l = fmaf(t[j], sW2[j * 32 + c], l);
    l += sb2[c];
    float val = l + gumbel_at(k0, k1, (unsigned)(v * 32 + c), 2u * (unsigned)NN * 32u);
    if (val > best) { best = val; bi = c; }
  }
  outp[(long long)NN + v] = (float)bi;
}

// ---------------- launch ------------------------------------------------------
extern "C" void kernel_launch(void* const* d_in, const int* in_sizes, int n_in,
                              void* d_out, int out_size) {
  (void)out_size;
  static const int SZ_DICT[17] = {12800000, 6400000, 32, 2048, 16, 384, 24,
                                  768, 32, 512, 16, 512, 32, 768, 24, 768, 32};
  static const int SZ_ALPHA[17] = {2048, 384, 768, 768, 768, 512, 512, 16, 24,
                                   32, 24, 32, 16, 32, 32, 6400000, 12800000};
  int match_dict = (n_in >= 17), match_alpha = (n_in >= 17);
  for (int i = 0; i < 17 && i < n_in; i++) {
    if (in_sizes[i] != SZ_DICT[i])  match_dict = 0;
    if (in_sizes[i] != SZ_ALPHA[i]) match_alpha = 0;
  }

  const float *x, *W1, *b1, *W2, *b2, *W3, *b3;
  const float *Ws1, *bs1, *Ws2, *bs2, *We1, *be1, *We2, *be2;
  const void* ei;
  if (match_alpha && !match_dict) {
    W1  = (const float*)d_in[0];  W2  = (const float*)d_in[1];
    W3  = (const float*)d_in[2];  We1 = (const float*)d_in[3];
    We2 = (const float*)d_in[4];  Ws1 = (const float*)d_in[5];
    Ws2 = (const float*)d_in[6];  b1  = (const float*)d_in[7];
    b2  = (const float*)d_in[8];  b3  = (const float*)d_in[9];
    be1 = (const float*)d_in[10]; be2 = (const float*)d_in[11];
    bs1 = (const float*)d_in[12]; bs2 = (const float*)d_in[13];
    ei  = d_in[15];               x   = (const float*)d_in[16];
  } else {
    x   = (const float*)d_in[0];  ei  = d_in[1];
    W1  = (const float*)d_in[3];  b1  = (const float*)d_in[4];
    W2  = (const float*)d_in[5];  b2  = (const float*)d_in[6];
    W3  = (const float*)d_in[7];  b3  = (const float*)d_in[8];
    Ws1 = (const float*)d_in[9];  bs1 = (const float*)d_in[10];
    Ws2 = (const float*)d_in[11]; bs2 = (const float*)d_in[12];
    We1 = (const float*)d_in[13]; be1 = (const float*)d_in[14];
    We2 = (const float*)d_in[15]; be2 = (const float*)d_in[16];
  }
  float* out = (float*)d_out;

  const int TB = 256;
  const int GB_W = (NN * 32 + TB - 1) / TB;      // warp-per-node: 12500
  const int GB_W2 = (NN * 16 + TB - 1) / TB;     // 2 nodes/warp: 6250

  k_init<<<NB_SCAN, 256>>>(ei);                              // 0
  k_lin<128, 16, 128, 0><<<(NN + 127) / 128, 128>>>(x, W1);  // 1 (independent)
  k_build<<<NB_SCAN, 256>>>(ei);                             // 2
  k_sort<<<(NN + 7) / 8, 256>>>();                           // 3 <-- ncu capture

  k_prop16<<<GB_W2, TB>>>(b1);
  k_lin<16, 24, 32, 1><<<(NN + 127) / 128, 128>>>(nullptr, W2);
  k_prop<24><<<GB_W, TB>>>(b2);
  k_lin<24, 32, 32, 1><<<(NN + 127) / 128, 128>>>(nullptr, W3);
  k_prop<32><<<GB_W, TB>>>(b3);

  k_start<<<(NN + 127) / 128, 128>>>(Ws1, bs1, Ws2, bs2, out);
  k_end<<<(2 * NN + 127) / 128, 128>>>(We1, be1, We2, be2, out);
}

// round 16
// speedup vs baseline: 1.0891x; 1.0180x over previous
#include <cuda_runtime.h>
#include <stdint.h>
#include <limits.h>

#define NN 100000
#define EE 3200000
#define PARTITIONABLE 1
#define NB_SCAN 391          // ceil(NN/256); also k_build grid (all co-resident)
#define NT_BUILD (NB_SCAN * 256)

// ---------------- scratch (static device globals; no allocations) -------------
static __device__ float g_bufA[NN * 32];   // linear outputs (stride 32)
static __device__ float g_bufB[NN * 32];   // propagated outputs (stride 32)
static __device__ float g_dinv[NN];
static __device__ int   g_cnt[NN];
static __device__ int   g_rowptr[NN + 1];
static __device__ int   g_cursor[NN];
static __device__ int   g_col[EE];
static __device__ int   g_pos[EE];
static __device__ int   g_bsum[512];
static __device__ int   g_boff[512];
static __device__ int   g_barrier;         // grid-sync counter (reset by k_init)
static __device__ unsigned g_keys[4];
static __device__ int   g_emode;           // 0=int32, 1=int64, 2=float32

// ---------------- threefry2x32 (JAX-exact) ------------------------------------
__device__ __forceinline__ void tf2x32(unsigned k0, unsigned k1,
                                       unsigned x0, unsigned x1,
                                       unsigned &o0, unsigned &o1) {
  unsigned ks2 = k0 ^ k1 ^ 0x1BD11BDAu;
  x0 += k0; x1 += k1;
#define TF_ROUND(r) { x0 += x1; x1 = (x1 << (r)) | (x1 >> (32 - (r))); x1 ^= x0; }
  TF_ROUND(13) TF_ROUND(15) TF_ROUND(26) TF_ROUND(6)
  x0 += k1;  x1 += ks2 + 1u;
  TF_ROUND(17) TF_ROUND(29) TF_ROUND(16) TF_ROUND(24)
  x0 += ks2; x1 += k0 + 2u;
  TF_ROUND(13) TF_ROUND(15) TF_ROUND(26) TF_ROUND(6)
  x0 += k0;  x1 += k1 + 3u;
  TF_ROUND(17) TF_ROUND(29) TF_ROUND(16) TF_ROUND(24)
  x0 += k1;  x1 += ks2 + 4u;
  TF_ROUND(13) TF_ROUND(15) TF_ROUND(26) TF_ROUND(6)
  x0 += ks2; x1 += k0 + 5u;
#undef TF_ROUND
  o0 = x0; o1 = x1;
}

__device__ __forceinline__ float gumbel_at(unsigned k0, unsigned k1,
                                           unsigned idx, unsigned total) {
  unsigned bits;
#if PARTITIONABLE
  unsigned o0, o1; tf2x32(k0, k1, 0u, idx, o0, o1);
  bits = o0 ^ o1;
#else
  unsigned half = total >> 1;
  unsigned lane = (idx < half) ? idx : (idx - half);
  unsigned o0, o1; tf2x32(k0, k1, lane, lane + half, o0, o1);
  bits = (idx < half) ? o0 : o1;
#endif
  float f = __uint_as_float((bits >> 9) | 0x3F800000u) - 1.0f;
  float u = fmaxf(1.17549435e-38f, f + 1.17549435e-38f);
  return -logf(-logf(u));
}

__device__ __forceinline__ int edge_at(const void* __restrict__ ei, long long idx) {
  int m = g_emode;
  if (m == 0) return ((const int*)ei)[idx];
  if (m == 1) return (int)((const long long*)ei)[idx];
  return (int)((const float*)ei)[idx];
}

// ---------------- init: zero cnt + barrier + dtype sniff + PRNG keys ----------
__global__ void __launch_bounds__(256) k_init(const void* __restrict__ ei) {
  int i = blockIdx.x * blockDim.x + threadIdx.x;
  if (i < NN) g_cnt[i] = 0;
  if (blockIdx.x == 0 && threadIdx.x == 0) {
    g_barrier = 0;
    const unsigned* w = (const unsigned*)ei;
    int oddzero = 1;
    for (int k = 1; k < 128; k += 2) oddzero &= (w[k] == 0u);
    if (oddzero) { g_emode = 1; }
    else {
      int floaty = 1;
      for (int k = 0; k < 128; k++) {
        unsigned e = (w[k] >> 23) & 0xFFu;
        floaty &= (w[k] == 0u) || (e >= 0x70u);
      }
      g_emode = floaty ? 2 : 0;
    }
    unsigned a0, a1, b0, b1;
#if PARTITIONABLE
    tf2x32(0u, 42u, 0u, 0u, a0, a1);
    tf2x32(0u, 42u, 0u, 1u, b0, b1);
    g_keys[0] = a0; g_keys[1] = a1; g_keys[2] = b0; g_keys[3] = b1;
#else
    tf2x32(0u, 42u, 0u, 2u, a0, a1);
    tf2x32(0u, 42u, 1u, 3u, b0, b1);
    g_keys[0] = a0; g_keys[1] = b0; g_keys[2] = a1; g_keys[3] = b1;
#endif
  }
}

// ---------------- grid barrier (all NB_SCAN blocks resident) ------------------
__device__ __forceinline__ void gsync(int phase) {
  __syncthreads();
  __threadfence();
  if (threadIdx.x == 0) {
    atomicAdd(&g_barrier, 1);
    while (*(volatile int*)&g_barrier < NB_SCAN * phase) {}
  }
  __syncthreads();
}

// ---------------- fused hist + scan + fill (one persistent kernel) ------------
__global__ void __launch_bounds__(256) k_build(const void* __restrict__ ei) {
  int t = threadIdx.x;
  int tid = blockIdx.x * 256 + t;

  // phase 0: histogram (grid-strided, coalesced)
  for (long long e = tid; e < EE; e += NT_BUILD) {
    int d = edge_at(ei, (long long)EE + e);
    if ((unsigned)d < NN) atomicAdd(&g_cnt[d], 1);
  }
  gsync(1);

  // phase 1: per-block inclusive scan of this block's 256 counts
  __shared__ int sp[512];
  int i = blockIdx.x * 256 + t;
  int c = (i < NN) ? g_cnt[i] : 0;
  sp[t] = c;
  __syncthreads();
  for (int off = 1; off < 256; off <<= 1) {
    int a = sp[t];
    int b = (t >= off) ? sp[t - off] : 0;
    __syncthreads();
    sp[t] = a + b;
    __syncthreads();
  }
  int blocktot = sp[255];
  int myincl = sp[t];
  if (t == 0) g_bsum[blockIdx.x] = blocktot;
  gsync(2);

  // phase 2: block 0 scans the 391 block sums
  if (blockIdx.x == 0) {
    __syncthreads();
    int v0 = (t < NB_SCAN) ? g_bsum[t] : 0;
    int v1 = (t + 256 < NB_SCAN) ? g_bsum[t + 256] : 0;
    sp[t] = v0; sp[t + 256] = v1;
    __syncthreads();
    for (int off = 1; off < 512; off <<= 1) {
      int a0 = sp[t], a1 = sp[t + 256];
      int b0 = (t >= off) ? sp[t - off] : 0;
      int b1 = (t + 256 >= off) ? sp[t + 256 - off] : 0;
      __syncthreads();
      sp[t] = a0 + b0; sp[t + 256] = a1 + b1;
      __syncthreads();
    }
    if (t < NB_SCAN) g_boff[t] = sp[t] - v0;
    if (t + 256 < NB_SCAN) g_boff[t + 256] = sp[t + 256] - v1;
    if (t == 0) g_rowptr[NN] = sp[NB_SCAN - 1];
  }
  gsync(3);

  // phase 3: rowptr + cursor + dinv
  if (i < NN) {
    int excl = myincl - c + g_boff[blockIdx.x];
    g_rowptr[i] = excl;
    g_cursor[i] = excl;
    g_dinv[i] = 1.0f / sqrtf((float)c + 1.0f);   // matches reference bit-for-bit
  }
  gsync(4);

  // phase 4: fill (grid-strided)
  for (long long e = tid; e < EE; e += NT_BUILD) {
    int s = edge_at(ei, e);
    int d = edge_at(ei, (long long)EE + e);
    if ((unsigned)d < NN && (unsigned)s < NN) {
      int p = atomicAdd(&g_cursor[d], 1);
      g_col[p] = s;
      g_pos[p] = (int)e;
    }
  }
}

// ---------------- sort: warp bitonic, 32-bit key(pos)/payload(col) ------------
__global__ void __launch_bounds__(256) k_sort() {
  __shared__ int sp_[8][128];
  __shared__ int sc_[8][128];
  int wid = threadIdx.x >> 5, lane = threadIdx.x & 31;
  int v = blockIdx.x * 8 + wid;
  if (v >= NN) return;
  int s = g_rowptr[v], e = g_rowptr[v + 1], d = e - s;
  if (d <= 1) return;
  if (d <= 32) {
    // 32-wide bitonic, 1 elem/lane, 15 stages
    int kk = INT_MAX, cc = 0;
    if (lane < d) { kk = g_pos[s + lane]; cc = g_col[s + lane]; }
#pragma unroll
    for (int k = 2; k <= 32; k <<= 1) {
#pragma unroll
      for (int j = k >> 1; j > 0; j >>= 1) {
        int ok = __shfl_xor_sync(0xFFFFFFFFu, kk, j);
        int oc = __shfl_xor_sync(0xFFFFFFFFu, cc, j);
        bool lower = ((lane & j) == 0);
        bool up = ((lane & k) == 0);       // k=32: always true -> ascending
        bool takeMin = (lower == up);
        bool sw = takeMin ? (ok < kk) : (ok > kk);
        if (sw) { kk = ok; cc = oc; }
      }
    }
    if (lane < d) g_col[s + lane] = cc;
  } else if (d <= 64) {
    // 64-wide bitonic, 2 elems/lane (i0=lane, i1=lane+32), 21 stages
    int k0 = INT_MAX, c0 = 0, k1 = INT_MAX, c1 = 0;
    if (lane < d)      { k0 = g_pos[s + lane];      c0 = g_col[s + lane]; }
    if (lane + 32 < d) { k1 = g_pos[s + lane + 32]; c1 = g_col[s + lane + 32]; }
#pragma unroll
    for (int k = 2; k <= 64; k <<= 1) {
#pragma unroll
      for (int j = 32; j > 0; j >>= 1) {
        if (j >= k) continue;
        if (j == 32) {
          // k == 64 only: in-lane exchange, ascending, i0 < i1
          if (k1 < k0) {
            int tk = k0; k0 = k1; k1 = tk;
            int tc = c0; c0 = c1; c1 = tc;
          }
        } else {
          int o0k = __shfl_xor_sync(0xFFFFFFFFu, k0, j);
          int o0c = __shfl_xor_sync(0xFFFFFFFFu, c0, j);
          int o1k = __shfl_xor_sync(0xFFFFFFFFu, k1, j);
          int o1c = __shfl_xor_sync(0xFFFFFFFFu, c1, j);
          bool lower = ((lane & j) == 0);
          bool up0, up1;
          if (k == 64)      { up0 = true;              up1 = true; }
          else if (k == 32) { up0 = true;              up1 = false; }
          else              { up0 = ((lane & k) == 0); up1 = up0; }
          bool sw0 = (lower == up0) ? (o0k < k0) : (o0k > k0);
          bool sw1 = (lower == up1) ? (o1k < k1) : (o1k > k1);
          if (sw0) { k0 = o0k; c0 = o0c; }
          if (sw1) { k1 = o1k; c1 = o1c; }
        }
      }
    }
    if (lane < d)      g_col[s + lane]      = c0;
    if (lane + 32 < d) g_col[s + lane + 32] = c1;
  } else if (d <= 128) {
    int* ap = sp_[wid];
    int* ac = sc_[wid];
    for (int i = lane; i < d; i += 32) { ap[i] = g_pos[s + i]; ac[i] = g_col[s + i]; }
    __syncwarp();
    for (int p = 0; p < d; p++) {
      for (int i = (p & 1) + 2 * lane; i + 1 < d; i += 64) {
        int pa = ap[i], pb = ap[i + 1];
        if (pa > pb) {
          ap[i] = pb; ap[i + 1] = pa;
          int ca = ac[i]; ac[i] = ac[i + 1]; ac[i + 1] = ca;
        }
      }
      __syncwarp();
    }
    for (int i = lane; i < d; i += 32) g_col[s + i] = ac[i];
  } else {
    if (lane == 0) {
      for (int i = s + 1; i < e; i++) {
        int kp = g_pos[i], kc = g_col[i]; int j = i - 1;
        while (j >= s && g_pos[j] > kp) {
          g_pos[j + 1] = g_pos[j]; g_col[j + 1] = g_col[j]; j--;
        }
        g_pos[j + 1] = kp; g_col[j + 1] = kc;
      }
    }
  }
}

// ---------------- GCN linear: out(bufA) = in @ W  (no bias here) --------------
template<int K, int F, int INSTRIDE, int SRC>
__global__ void __launch_bounds__(128) k_lin(const float* __restrict__ xin,
                                             const float* __restrict__ W) {
  __shared__ float sW[K * F];
  for (int i = threadIdx.x; i < K * F; i += blockDim.x) sW[i] = W[i];
  __syncthreads();
  int v = blockIdx.x * blockDim.x + threadIdx.x;
  if (v >= NN) return;
  const float* in = (SRC == 0) ? (xin + (size_t)v * INSTRIDE)
                               : (g_bufB + (size_t)v * INSTRIDE);
  float acc[F];
#pragma unroll
  for (int f = 0; f < F; f++) acc[f] = 0.f;
#pragma unroll 4
  for (int k = 0; k < K; k++) {
    float xv = in[k];
#pragma unroll
    for (int f = 0; f < F; f++) acc[f] = fmaf(xv, sW[k * F + f], acc[f]);
  }
  float* o = g_bufA + (size_t)v * 32;
#pragma unroll
  for (int f = 0; f < F; f++) o[f] = acc[f];
}

// ---------------- propagate F=16: 2 nodes per warp, unroll-4 exact order ------
__global__ void __launch_bounds__(256) k_prop16(const float* __restrict__ b) {
  int gw = (blockIdx.x * blockDim.x + threadIdx.x) >> 5;
  int lane = threadIdx.x & 31;
  int half = lane >> 4;
  int l = lane & 15;
  int v = gw * 2 + half;
  if (v >= NN) return;
  float dv = g_dinv[v];
  int s = g_rowptr[v], e = g_rowptr[v + 1];
  float acc = 0.f;
  int j = s;
  for (; j + 3 < e; j += 4) {
    int u0 = g_col[j], u1 = g_col[j + 1], u2 = g_col[j + 2], u3 = g_col[j + 3];
    float w0 = __fmul_rn(g_dinv[u0], dv);
    float w1 = __fmul_rn(g_dinv[u1], dv);
    float w2 = __fmul_rn(g_dinv[u2], dv);
    float w3 = __fmul_rn(g_dinv[u3], dv);
    float h0 = g_bufA[u0 * 32 + l];
    float h1 = g_bufA[u1 * 32 + l];
    float h2 = g_bufA[u2 * 32 + l];
    float h3 = g_bufA[u3 * 32 + l];
    acc = __fadd_rn(acc, __fmul_rn(h0, w0));    // exact sequential order kept
    acc = __fadd_rn(acc, __fmul_rn(h1, w1));
    acc = __fadd_rn(acc, __fmul_rn(h2, w2));
    acc = __fadd_rn(acc, __fmul_rn(h3, w3));
  }
  for (; j < e; j++) {
    int u = g_col[j];
    float w = __fmul_rn(g_dinv[u], dv);
    acc = __fadd_rn(acc, __fmul_rn(g_bufA[u * 32 + l], w));
  }
  float sl = __fmul_rn(dv, dv);
  acc = __fadd_rn(acc, __fmul_rn(g_bufA[v * 32 + l], sl));
  g_bufB[v * 32 + l] = __fadd_rn(acc, b[l]);
}

// ---------------- propagate general (warp per node), unroll-4 exact order -----
template<int F>
__global__ void __launch_bounds__(256) k_prop(const float* __restrict__ b) {
  int gw = (blockIdx.x * blockDim.x + threadIdx.x) >> 5;
  int lane = threadIdx.x & 31;
  if (gw >= NN) return;
  int v = gw;
  float dv = g_dinv[v];
  int s = g_rowptr[v], e = g_rowptr[v + 1];
  float acc = 0.f;
  int j = s;
  for (; j + 3 < e; j += 4) {
    int u0 = g_col[j], u1 = g_col[j + 1], u2 = g_col[j + 2], u3 = g_col[j + 3];
    float w0 = __fmul_rn(g_dinv[u0], dv);
    float w1 = __fmul_rn(g_dinv[u1], dv);
    float w2 = __fmul_rn(g_dinv[u2], dv);
    float w3 = __fmul_rn(g_dinv[u3], dv);
    float h0 = (lane < F) ? g_bufA[u0 * 32 + lane] : 0.f;
    float h1 = (lane < F) ? g_bufA[u1 * 32 + lane] : 0.f;
    float h2 = (lane < F) ? g_bufA[u2 * 32 + lane] : 0.f;
    float h3 = (lane < F) ? g_bufA[u3 * 32 + lane] : 0.f;
    acc = __fadd_rn(acc, __fmul_rn(h0, w0));
    acc = __fadd_rn(acc, __fmul_rn(h1, w1));
    acc = __fadd_rn(acc, __fmul_rn(h2, w2));
    acc = __fadd_rn(acc, __fmul_rn(h3, w3));
  }
  for (; j < e; j++) {
    int u = g_col[j];
    float w = __fmul_rn(g_dinv[u], dv);
    float hv = (lane < F) ? g_bufA[u * 32 + lane] : 0.f;
    acc = __fadd_rn(acc, __fmul_rn(hv, w));
  }
  if (lane < F) {
    float sl = __fmul_rn(dv, dv);
    acc = __fadd_rn(acc, __fmul_rn(g_bufA[v * 32 + lane], sl));
    g_bufB[v * 32 + lane] = __fadd_rn(acc, b[lane]);
  }
}

// ---------------- start head --------------------------------------------------
__global__ void __launch_bounds__(128) k_start(
    const float* __restrict__ Ws1, const float* __restrict__ bs1,
    const float* __restrict__ Ws2, const float* __restrict__ bs2,
    float* __restrict__ outp) {
  __shared__ float sW1[512], sW2[512], sb1[16], sb2[32];
  for (int i = threadIdx.x; i < 512; i += blockDim.x) { sW1[i] = Ws1[i]; sW2[i] = Ws2[i]; }
  if (threadIdx.x < 16) sb1[threadIdx.x] = bs1[threadIdx.x];
  if (threadIdx.x < 32) sb2[threadIdx.x] = bs2[threadIdx.x];
  __syncthreads();
  int v = blockIdx.x * blockDim.x + threadIdx.x;
  if (v >= NN) return;
  float hr[32];
#pragma unroll
  for (int k = 0; k < 32; k++) hr[k] = g_bufB[v * 32 + k];
  float t[16];
#pragma unroll
  for (int j = 0; j < 16; j++) {
    float a = 0.f;
#pragma unroll
    for (int k = 0; k < 32; k++) a = fmaf(hr[k], sW1[k * 16 + j], a);
    a += sb1[j];
    t[j] = fminf(fmaxf(a, 0.f), 6.f);
  }
  unsigned k0 = g_keys[0], k1 = g_keys[1];
  float best = -1e30f; int bi = 0;
  for (int c = 0; c < 32; c++) {
    float l = 0.f;
#pragma unroll
    for (int j = 0; j < 16; j++) l = fmaf(t[j], sW2[j * 32 + c], l);
    l += sb2[c];
    float val = l + gumbel_at(k0, k1, (unsigned)(v * 32 + c), (unsigned)NN * 32u);
    if (val > best) { best = val; bi = c; }
  }
  outp[v] = (float)bi;
}

// ---------------- end head ----------------------------------------------------
__global__ void __launch_bounds__(128) k_end(
    const float* __restrict__ We1, const float* __restrict__ be1,
    const float* __restrict__ We2, const float* __restrict__ be2,
    float* __restrict__ outp) {
  __shared__ float sW1[768], sW2[768], sb1[24], sb2[32];
  for (int i = threadIdx.x; i < 768; i += blockDim.x) { sW1[i] = We1[i]; sW2[i] = We2[i]; }
  if (threadIdx.x < 24) sb1[threadIdx.x] = be1[threadIdx.x];
  if (threadIdx.x < 32) sb2[threadIdx.x] = be2[threadIdx.x];
  __syncthreads();
  int v = blockIdx.x * blockDim.x + threadIdx.x;
  if (v >= 2 * NN) return;
  int row = (v < NN) ? v : (int)outp[v - NN];
  float hr[32];
#pragma unroll
  for (int k = 0; k < 32; k++) hr[k] = g_bufB[row * 32 + k];
  float t[24];
#pragma unroll
  for (int j = 0; j < 24; j++) {
    float a = 0.f;
#pragma unroll
    for (int k = 0; k < 32; k++) a = fmaf(hr[k], sW1[k * 24 + j], a);
    a += sb1[j];
    t[j] = fminf(fmaxf(a, 0.f), 6.f);
  }
  unsigned k0 = g_keys[2], k1 = g_keys[3];
  float best = -1e30f; int bi = 0;
  for (int c = 0; c < 32; c++) {
    float l = 0.f;
#pragma unroll
    for (int j = 0; j < 24; j++) l = fmaf(t[j], sW2[j * 32 + c], l);
    l += sb2[c];
    float val = l + gumbel_at(k0, k1, (unsigned)(v * 32 + c), 2u * (unsigned)NN * 32u);
    if (val > best) { best = val; bi = c; }
  }
  outp[(long long)NN + v] = (float)bi;
}

// ---------------- launch ------------------------------------------------------
extern "C" void kernel_launch(void* const* d_in, const int* in_sizes, int n_in,
                              void* d_out, int out_size) {
  (void)out_size;
  static const int SZ_DICT[17] = {12800000, 6400000, 32, 2048, 16, 384, 24,
                                  768, 32, 512, 16, 512, 32, 768, 24, 768, 32};
  static const int SZ_ALPHA[17] = {2048, 384, 768, 768, 768, 512, 512, 16, 24,
                                   32, 24, 32, 16, 32, 32, 6400000, 12800000};
  int match_dict = (n_in >= 17), match_alpha = (n_in >= 17);
  for (int i = 0; i < 17 && i < n_in; i++) {
    if (in_sizes[i] != SZ_DICT[i])  match_dict = 0;
    if (in_sizes[i] != SZ_ALPHA[i]) match_alpha = 0;
  }

  const float *x, *W1, *b1, *W2, *b2, *W3, *b3;
  const float *Ws1, *bs1, *Ws2, *bs2, *We1, *be1, *We2, *be2;
  const void* ei;
  if (match_alpha && !match_dict) {
    W1  = (const float*)d_in[0];  W2  = (const float*)d_in[1];
    W3  = (const float*)d_in[2];  We1 = (const float*)d_in[3];
    We2 = (const float*)d_in[4];  Ws1 = (const float*)d_in[5];
    Ws2 = (const float*)d_in[6];  b1  = (const float*)d_in[7];
    b2  = (const float*)d_in[8];  b3  = (const float*)d_in[9];
    be1 = (const float*)d_in[10]; be2 = (const float*)d_in[11];
    bs1 = (const float*)d_in[12]; bs2 = (const float*)d_in[13];
    ei  = d_in[15];               x   = (const float*)d_in[16];
  } else {
    x   = (const float*)d_in[0];  ei  = d_in[1];
    W1  = (const float*)d_in[3];  b1  = (const float*)d_in[4];
    W2  = (const float*)d_in[5];  b2  = (const float*)d_in[6];
    W3  = (const float*)d_in[7];  b3  = (const float*)d_in[8];
    Ws1 = (const float*)d_in[9];  bs1 = (const float*)d_in[10];
    Ws2 = (const float*)d_in[11]; bs2 = (const float*)d_in[12];
    We1 = (const float*)d_in[13]; be1 = (const float*)d_in[14];
    We2 = (const float*)d_in[15]; be2 = (const float*)d_in[16];
  }
  float* out = (float*)d_out;

  const int TB = 256;
  const int GB_W = (NN * 32 + TB - 1) / TB;      // warp-per-node: 12500
  const int GB_W2 = (NN * 16 + TB - 1) / TB;     // 2 nodes/warp: 6250

  k_init<<<NB_SCAN, 256>>>(ei);                              // 0
  k_lin<128, 16, 128, 0><<<(NN + 127) / 128, 128>>>(x, W1);  // 1 (independent)
  k_build<<<NB_SCAN, 256>>>(ei);                             // 2
  k_sort<<<(NN + 7) / 8, 256>>>();                           // 3 <-- ncu capture

  k_prop16<<<GB_W2, TB>>>(b1);
  k_lin<16, 24, 32, 1><<<(NN + 127) / 128, 128>>>(nullptr, W2);
  k_prop<24><<<GB_W, TB>>>(b2);
  k_lin<24, 32, 32, 1><<<(NN + 127) / 128, 128>>>(nullptr, W3);
  k_prop<32><<<GB_W, TB>>>(b3);

  k_start<<<(NN + 127) / 128, 128>>>(Ws1, bs1, Ws2, bs2, out);
  k_end<<<(2 * NN + 127) / 128, 128>>>(We1, be1, We2, be2, out);
}